// round 2
// baseline (speedup 1.0000x reference)
#include <cuda_runtime.h>
#include <math.h>

// Problem constants (fixed by setup_inputs)
#define T_TOKENS 4096
#define H_DIM    1024
#define I_DIM    4096
#define N_EXP    8
#define TOPK     2
#define OUT_ELEMS  (T_TOKENS * H_DIM)            // 4,194,304
#define LOGITS_OFF OUT_ELEMS                     // router_logits [T, E]
#define AUX_OFF    (OUT_ELEMS + T_TOKENS * N_EXP)// aux_loss scalar
#define MAXROWS  (T_TOKENS * TOPK)               // 8192 dispatched rows

#define BM 64
#define BN 64
#define BK 16
#define MAXTILES 136   // worst case sum_e ceil(ne/64) <= 128 + 7

// ---------------- device scratch (no allocation allowed) ----------------
__device__ float g_hbuf[(size_t)MAXROWS * I_DIM];   // 128 MiB intermediate h
__device__ int   g_counts[N_EXP];
__device__ int   g_offsets[N_EXP];
__device__ int   g_cursor[N_EXP];
__device__ int   g_tok[MAXROWS];
__device__ float g_gate[MAXROWS];
__device__ int   g_top_idx[T_TOKENS * TOPK];
__device__ float g_top_gate[T_TOKENS * TOPK];
__device__ float g_accp[N_EXP];
__device__ float g_zsum;
__device__ int   g_tile_e[MAXTILES];
__device__ int   g_tile_m[MAXTILES];

// ---------------- init ----------------
__global__ void init_kernel() {
    int i = threadIdx.x;
    if (i < N_EXP) {
        g_counts[i] = 0;
        g_cursor[i] = 0;
        g_accp[i]   = 0.f;
    }
    if (i == 0) g_zsum = 0.f;
}

// ---------------- router: logits, top-2 gates, aux stats ----------------
__global__ void router_kernel(const float* __restrict__ x,
                              const float* __restrict__ wg,
                              float* __restrict__ out) {
    __shared__ float sl[N_EXP];
    const int t   = blockIdx.x;
    const int tid = threadIdx.x;
    if (tid < N_EXP) sl[tid] = 0.f;
    __syncthreads();

    float p[N_EXP];
#pragma unroll
    for (int e = 0; e < N_EXP; e++) p[e] = 0.f;

    const float* xr = x + (size_t)t * H_DIM;
    for (int h = tid; h < H_DIM; h += blockDim.x) {
        float xv = xr[h];
#pragma unroll
        for (int e = 0; e < N_EXP; e++) p[e] += xv * wg[h * N_EXP + e];
    }
    // warp reduce then smem atomics
#pragma unroll
    for (int off = 16; off > 0; off >>= 1) {
#pragma unroll
        for (int e = 0; e < N_EXP; e++)
            p[e] += __shfl_down_sync(0xffffffffu, p[e], off);
    }
    if ((tid & 31) == 0) {
#pragma unroll
        for (int e = 0; e < N_EXP; e++) atomicAdd(&sl[e], p[e]);
    }
    __syncthreads();

    if (tid == 0) {
        float l[N_EXP];
#pragma unroll
        for (int e = 0; e < N_EXP; e++) {
            l[e] = sl[e];
            out[LOGITS_OFF + t * N_EXP + e] = l[e];
        }
        // top-2 (stable: first index wins ties, matching lax.top_k)
        int i0 = 0; float v0 = l[0];
#pragma unroll
        for (int e = 1; e < N_EXP; e++) if (l[e] > v0) { v0 = l[e]; i0 = e; }
        int i1 = -1; float v1 = -1e30f;
#pragma unroll
        for (int e = 0; e < N_EXP; e++) if (e != i0 && l[e] > v1) { v1 = l[e]; i1 = e; }
        float g0 = 1.f / (1.f + expf(v1 - v0));
        float g1 = 1.f - g0;
        g_top_idx[2 * t]      = i0;  g_top_gate[2 * t]      = g0;
        g_top_idx[2 * t + 1]  = i1;  g_top_gate[2 * t + 1]  = g1;
        atomicAdd(&g_counts[i0], 1);
        atomicAdd(&g_counts[i1], 1);
        // full softmax for acc_probs + logsumexp for z-loss
        float m = l[0];
#pragma unroll
        for (int e = 1; e < N_EXP; e++) m = fmaxf(m, l[e]);
        float den = 0.f;
#pragma unroll
        for (int e = 0; e < N_EXP; e++) den += expf(l[e] - m);
#pragma unroll
        for (int e = 0; e < N_EXP; e++) atomicAdd(&g_accp[e], expf(l[e] - m) / den);
        float lse = m + logf(den);
        atomicAdd(&g_zsum, lse * lse);
    }
}

// ---------------- offsets + tile worklist ----------------
__global__ void build_kernel() {
    int off = 0;
    for (int e = 0; e < N_EXP; e++) { g_offsets[e] = off; off += g_counts[e]; }
    int gm = 0;
    for (int e = 0; e < N_EXP; e++) {
        int nt = (g_counts[e] + BM - 1) / BM;
        for (int i = 0; i < nt && gm < MAXTILES; i++) {
            g_tile_e[gm] = e; g_tile_m[gm] = i; gm++;
        }
    }
    for (; gm < MAXTILES; gm++) g_tile_e[gm] = -1;
}

// ---------------- scatter tokens into per-expert groups ----------------
__global__ void scatter_kernel() {
    int t = blockIdx.x * blockDim.x + threadIdx.x;
    if (t >= T_TOKENS) return;
#pragma unroll
    for (int k = 0; k < TOPK; k++) {
        int e   = g_top_idx[2 * t + k];
        int pos = atomicAdd(&g_cursor[e], 1);
        int idx = g_offsets[e] + pos;
        g_tok[idx]  = t;
        g_gate[idx] = g_top_gate[2 * t + k];
    }
}

// ---------------- GEMM1: h = gelu(x_gathered @ w_fc[e]^T + b_fc[e]) ----------------
__global__ __launch_bounds__(256) void gemm1_kernel(const float* __restrict__ x,
                                                    const float* __restrict__ w_fc,
                                                    const float* __restrict__ b_fc) {
    const int e = g_tile_e[blockIdx.y];
    if (e < 0) return;
    const int ne   = g_counts[e];
    const int base = g_offsets[e];
    const int row0 = g_tile_m[blockIdx.y] * BM;
    const int n0   = blockIdx.x * BN;
    const float* Bp = w_fc + (size_t)e * I_DIM * H_DIM;

    __shared__ float As[BM][BK + 1];
    __shared__ float Bs[BN][BK + 1];
    __shared__ int   toks[BM];

    const int tid = threadIdx.x;
    if (tid < BM) {
        int r = row0 + tid;
        toks[tid] = g_tok[base + (r < ne ? r : 0)];
    }
    __syncthreads();

    const int arow = tid >> 2;
    const int acol = (tid & 3) * 4;
    const int ty = tid >> 4, tx = tid & 15;
    const size_t a_base = (size_t)toks[arow] * H_DIM + acol;
    const size_t b_base = (size_t)(n0 + arow) * H_DIM + acol;

    float acc[4][4];
#pragma unroll
    for (int i = 0; i < 4; i++)
#pragma unroll
        for (int j = 0; j < 4; j++) acc[i][j] = 0.f;

    for (int k0 = 0; k0 < H_DIM; k0 += BK) {
        float4 av = *(const float4*)(x  + a_base + k0);
        float4 bv = *(const float4*)(Bp + b_base + k0);
        As[arow][acol] = av.x; As[arow][acol + 1] = av.y;
        As[arow][acol + 2] = av.z; As[arow][acol + 3] = av.w;
        Bs[arow][acol] = bv.x; Bs[arow][acol + 1] = bv.y;
        Bs[arow][acol + 2] = bv.z; Bs[arow][acol + 3] = bv.w;
        __syncthreads();
#pragma unroll
        for (int kk = 0; kk < BK; kk++) {
            float a[4], b[4];
#pragma unroll
            for (int i = 0; i < 4; i++) a[i] = As[ty * 4 + i][kk];
#pragma unroll
            for (int j = 0; j < 4; j++) b[j] = Bs[tx * 4 + j][kk];
#pragma unroll
            for (int i = 0; i < 4; i++)
#pragma unroll
                for (int j = 0; j < 4; j++) acc[i][j] += a[i] * b[j];
        }
        __syncthreads();
    }

#pragma unroll
    for (int i = 0; i < 4; i++) {
        int r = row0 + ty * 4 + i;
        if (r < ne) {
            size_t hrow = (size_t)(base + r) * I_DIM;
#pragma unroll
            for (int j = 0; j < 4; j++) {
                int c = n0 + tx * 4 + j;
                float v = acc[i][j] + b_fc[e * I_DIM + c];
                v = 0.5f * v * (1.0f + erff(v * 0.7071067811865476f));
                g_hbuf[hrow + c] = v;
            }
        }
    }
}

// ---------------- GEMM2: out += gate * (h @ w_proj[e]^T + b_proj[e]) ----------------
__global__ __launch_bounds__(256) void gemm2_kernel(const float* __restrict__ w_proj,
                                                    const float* __restrict__ b_proj,
                                                    float* __restrict__ out) {
    const int e = g_tile_e[blockIdx.y];
    if (e < 0) return;
    const int ne   = g_counts[e];
    const int base = g_offsets[e];
    const int row0 = g_tile_m[blockIdx.y] * BM;
    const int n0   = blockIdx.x * BN;
    const float* Bp = w_proj + (size_t)e * H_DIM * I_DIM;

    __shared__ float As[BM][BK + 1];
    __shared__ float Bs[BN][BK + 1];
    __shared__ int   toks[BM];
    __shared__ float sgate[BM];

    const int tid = threadIdx.x;
    if (tid < BM) {
        int r = row0 + tid;
        int rr = (r < ne ? r : 0);
        toks[tid]  = g_tok[base + rr];
        sgate[tid] = g_gate[base + rr];
    }
    __syncthreads();

    const int arow = tid >> 2;
    const int acol = (tid & 3) * 4;
    const int ty = tid >> 4, tx = tid & 15;
    int rA = row0 + arow; rA = (rA < ne ? rA : 0);
    const size_t a_base = (size_t)(base + rA) * I_DIM + acol;
    const size_t b_base = (size_t)(n0 + arow) * I_DIM + acol;

    float acc[4][4];
#pragma unroll
    for (int i = 0; i < 4; i++)
#pragma unroll
        for (int j = 0; j < 4; j++) acc[i][j] = 0.f;

    for (int k0 = 0; k0 < I_DIM; k0 += BK) {
        float4 av = *(const float4*)(g_hbuf + a_base + k0);
        float4 bv = *(const float4*)(Bp     + b_base + k0);
        As[arow][acol] = av.x; As[arow][acol + 1] = av.y;
        As[arow][acol + 2] = av.z; As[arow][acol + 3] = av.w;
        Bs[arow][acol] = bv.x; Bs[arow][acol + 1] = bv.y;
        Bs[arow][acol + 2] = bv.z; Bs[arow][acol + 3] = bv.w;
        __syncthreads();
#pragma unroll
        for (int kk = 0; kk < BK; kk++) {
            float a[4], b[4];
#pragma unroll
            for (int i = 0; i < 4; i++) a[i] = As[ty * 4 + i][kk];
#pragma unroll
            for (int j = 0; j < 4; j++) b[j] = Bs[tx * 4 + j][kk];
#pragma unroll
            for (int i = 0; i < 4; i++)
#pragma unroll
                for (int j = 0; j < 4; j++) acc[i][j] += a[i] * b[j];
        }
        __syncthreads();
    }

#pragma unroll
    for (int i = 0; i < 4; i++) {
        int r = row0 + ty * 4 + i;
        if (r < ne) {
            int   tok = toks[ty * 4 + i];
            float g   = sgate[ty * 4 + i];
#pragma unroll
            for (int j = 0; j < 4; j++) {
                int c = n0 + tx * 4 + j;
                float v = acc[i][j] + b_proj[e * H_DIM + c];
                atomicAdd(out + (size_t)tok * H_DIM + c, g * v);
            }
        }
    }
}

// ---------------- aux loss ----------------
__global__ void aux_kernel(float* __restrict__ out) {
    float sumA = 0.f, sumF = 0.f;
    for (int e = 0; e < N_EXP; e++) {
        sumA += fabsf(g_accp[e]);
        sumF += fabsf((float)g_counts[e]);
    }
    float sw = 0.f;
    for (int e = 0; e < N_EXP; e++)
        sw += (g_accp[e] / sumA) * ((float)g_counts[e] / sumF);
    sw *= (float)N_EXP;
    float z = g_zsum / (float)T_TOKENS;
    out[AUX_OFF] = sw + 0.1f * z;
}

// ---------------- launch ----------------
extern "C" void kernel_launch(void* const* d_in, const int* in_sizes, int n_in,
                              void* d_out, int out_size) {
    const float* x      = (const float*)d_in[0];
    const float* wg     = (const float*)d_in[1];
    const float* w_fc   = (const float*)d_in[2];
    const float* b_fc   = (const float*)d_in[3];
    const float* w_proj = (const float*)d_in[4];
    const float* b_proj = (const float*)d_in[5];
    float* out = (float*)d_out;

    cudaMemsetAsync(out, 0, (size_t)OUT_ELEMS * sizeof(float), 0);
    init_kernel<<<1, 32>>>();
    router_kernel<<<T_TOKENS, 128>>>(x, wg, out);
    build_kernel<<<1, 1>>>();
    scatter_kernel<<<T_TOKENS / 128, 128>>>();
    gemm1_kernel<<<dim3(I_DIM / BN, MAXTILES), 256>>>(x, w_fc, b_fc);
    gemm2_kernel<<<dim3(H_DIM / BN, MAXTILES), 256>>>(w_proj, b_proj, out);
    aux_kernel<<<1, 1>>>(out);
}

// round 3
// speedup vs baseline: 1.0544x; 1.0544x over previous
#include <cuda_runtime.h>
#include <math.h>

// Problem constants (fixed by setup_inputs)
#define T_TOKENS 4096
#define H_DIM    1024
#define I_DIM    4096
#define N_EXP    8
#define TOPK     2
#define OUT_ELEMS  (T_TOKENS * H_DIM)            // 4,194,304
#define LOGITS_OFF OUT_ELEMS                     // router_logits [T, E]
#define AUX_OFF    (OUT_ELEMS + T_TOKENS * N_EXP)// aux_loss scalar
#define MAXROWS  (T_TOKENS * TOPK)               // 8192 dispatched rows

#define BM 64
#define BN 64
#define BK 16
#define MAXTILES 136   // worst case sum_e ceil(ne/64) <= 128 + 7

// ---------------- device scratch (no allocation allowed) ----------------
__device__ float g_hbuf[(size_t)MAXROWS * I_DIM];   // 128 MiB intermediate h
__device__ int   g_counts[N_EXP];
__device__ int   g_offsets[N_EXP];
__device__ int   g_cursor[N_EXP];
__device__ int   g_tok[MAXROWS];
__device__ float g_gate[MAXROWS];
__device__ int   g_top_idx[T_TOKENS * TOPK];
__device__ float g_top_gate[T_TOKENS * TOPK];
__device__ float g_accp[N_EXP];
__device__ float g_zsum;
__device__ int   g_tile_e[MAXTILES];
__device__ int   g_tile_m[MAXTILES];

// ---------------- init ----------------
__global__ void init_kernel() {
    int i = threadIdx.x;
    if (i < N_EXP) {
        g_counts[i] = 0;
        g_cursor[i] = 0;
        g_accp[i]   = 0.f;
    }
    if (i == 0) g_zsum = 0.f;
}

// ---------------- router: logits, top-2 gates, aux stats ----------------
__global__ void router_kernel(const float* __restrict__ x,
                              const float* __restrict__ wg,
                              float* __restrict__ out) {
    __shared__ float sl[N_EXP];
    const int t   = blockIdx.x;
    const int tid = threadIdx.x;
    if (tid < N_EXP) sl[tid] = 0.f;
    __syncthreads();

    float p[N_EXP];
#pragma unroll
    for (int e = 0; e < N_EXP; e++) p[e] = 0.f;

    const float* xr = x + (size_t)t * H_DIM;
    for (int h = tid; h < H_DIM; h += blockDim.x) {
        float xv = xr[h];
#pragma unroll
        for (int e = 0; e < N_EXP; e++) p[e] += xv * wg[h * N_EXP + e];
    }
    // warp reduce then smem atomics
#pragma unroll
    for (int off = 16; off > 0; off >>= 1) {
#pragma unroll
        for (int e = 0; e < N_EXP; e++)
            p[e] += __shfl_down_sync(0xffffffffu, p[e], off);
    }
    if ((tid & 31) == 0) {
#pragma unroll
        for (int e = 0; e < N_EXP; e++) atomicAdd(&sl[e], p[e]);
    }
    __syncthreads();

    if (tid == 0) {
        float l[N_EXP];
#pragma unroll
        for (int e = 0; e < N_EXP; e++) {
            l[e] = sl[e];
            out[LOGITS_OFF + t * N_EXP + e] = l[e];
        }
        // top-2 (stable: first index wins ties, matching lax.top_k)
        int i0 = 0; float v0 = l[0];
#pragma unroll
        for (int e = 1; e < N_EXP; e++) if (l[e] > v0) { v0 = l[e]; i0 = e; }
        int i1 = -1; float v1 = -1e30f;
#pragma unroll
        for (int e = 0; e < N_EXP; e++) if (e != i0 && l[e] > v1) { v1 = l[e]; i1 = e; }
        float g0 = 1.f / (1.f + expf(v1 - v0));
        float g1 = 1.f - g0;
        g_top_idx[2 * t]      = i0;  g_top_gate[2 * t]      = g0;
        g_top_idx[2 * t + 1]  = i1;  g_top_gate[2 * t + 1]  = g1;
        atomicAdd(&g_counts[i0], 1);
        atomicAdd(&g_counts[i1], 1);
        // full softmax for acc_probs + logsumexp for z-loss
        float m = l[0];
#pragma unroll
        for (int e = 1; e < N_EXP; e++) m = fmaxf(m, l[e]);
        float den = 0.f;
#pragma unroll
        for (int e = 0; e < N_EXP; e++) den += expf(l[e] - m);
#pragma unroll
        for (int e = 0; e < N_EXP; e++) atomicAdd(&g_accp[e], expf(l[e] - m) / den);
        float lse = m + logf(den);
        atomicAdd(&g_zsum, lse * lse);
    }
}

// ---------------- offsets + tile worklist ----------------
__global__ void build_kernel() {
    int off = 0;
    for (int e = 0; e < N_EXP; e++) { g_offsets[e] = off; off += g_counts[e]; }
    int gm = 0;
    for (int e = 0; e < N_EXP; e++) {
        int nt = (g_counts[e] + BM - 1) / BM;
        for (int i = 0; i < nt && gm < MAXTILES; i++) {
            g_tile_e[gm] = e; g_tile_m[gm] = i; gm++;
        }
    }
    for (; gm < MAXTILES; gm++) g_tile_e[gm] = -1;
}

// ---------------- scatter tokens into per-expert groups ----------------
__global__ void scatter_kernel() {
    int t = blockIdx.x * blockDim.x + threadIdx.x;
    if (t >= T_TOKENS) return;
#pragma unroll
    for (int k = 0; k < TOPK; k++) {
        int e   = g_top_idx[2 * t + k];
        int pos = atomicAdd(&g_cursor[e], 1);
        int idx = g_offsets[e] + pos;
        g_tok[idx]  = t;
        g_gate[idx] = g_top_gate[2 * t + k];
    }
}

// ---------------- GEMM1: h = gelu(x_gathered @ w_fc[e]^T + b_fc[e]) ----------------
__global__ __launch_bounds__(256) void gemm1_kernel(const float* __restrict__ x,
                                                    const float* __restrict__ w_fc,
                                                    const float* __restrict__ b_fc) {
    const int e = g_tile_e[blockIdx.y];
    if (e < 0) return;
    const int ne   = g_counts[e];
    const int base = g_offsets[e];
    const int row0 = g_tile_m[blockIdx.y] * BM;
    const int n0   = blockIdx.x * BN;
    const float* Bp = w_fc + (size_t)e * I_DIM * H_DIM;

    __shared__ float As[BM][BK + 1];
    __shared__ float Bs[BN][BK + 1];
    __shared__ int   toks[BM];

    const int tid = threadIdx.x;
    if (tid < BM) {
        int r = row0 + tid;
        toks[tid] = g_tok[base + (r < ne ? r : 0)];
    }
    __syncthreads();

    const int arow = tid >> 2;
    const int acol = (tid & 3) * 4;
    const int ty = tid >> 4, tx = tid & 15;
    const size_t a_base = (size_t)toks[arow] * H_DIM + acol;
    const size_t b_base = (size_t)(n0 + arow) * H_DIM + acol;

    float acc[4][4];
#pragma unroll
    for (int i = 0; i < 4; i++)
#pragma unroll
        for (int j = 0; j < 4; j++) acc[i][j] = 0.f;

    for (int k0 = 0; k0 < H_DIM; k0 += BK) {
        float4 av = *(const float4*)(x  + a_base + k0);
        float4 bv = *(const float4*)(Bp + b_base + k0);
        As[arow][acol] = av.x; As[arow][acol + 1] = av.y;
        As[arow][acol + 2] = av.z; As[arow][acol + 3] = av.w;
        Bs[arow][acol] = bv.x; Bs[arow][acol + 1] = bv.y;
        Bs[arow][acol + 2] = bv.z; Bs[arow][acol + 3] = bv.w;
        __syncthreads();
#pragma unroll
        for (int kk = 0; kk < BK; kk++) {
            float a[4], b[4];
#pragma unroll
            for (int i = 0; i < 4; i++) a[i] = As[ty * 4 + i][kk];
#pragma unroll
            for (int j = 0; j < 4; j++) b[j] = Bs[tx * 4 + j][kk];
#pragma unroll
            for (int i = 0; i < 4; i++)
#pragma unroll
                for (int j = 0; j < 4; j++) acc[i][j] += a[i] * b[j];
        }
        __syncthreads();
    }

#pragma unroll
    for (int i = 0; i < 4; i++) {
        int r = row0 + ty * 4 + i;
        if (r < ne) {
            size_t hrow = (size_t)(base + r) * I_DIM;
#pragma unroll
            for (int j = 0; j < 4; j++) {
                int c = n0 + tx * 4 + j;
                float v = acc[i][j] + b_fc[e * I_DIM + c];
                v = 0.5f * v * (1.0f + erff(v * 0.7071067811865476f));
                g_hbuf[hrow + c] = v;
            }
        }
    }
}

// ---------------- GEMM2: out += gate * (h @ w_proj[e]^T + b_proj[e]) ----------------
__global__ __launch_bounds__(256) void gemm2_kernel(const float* __restrict__ w_proj,
                                                    const float* __restrict__ b_proj,
                                                    float* __restrict__ out) {
    const int e = g_tile_e[blockIdx.y];
    if (e < 0) return;
    const int ne   = g_counts[e];
    const int base = g_offsets[e];
    const int row0 = g_tile_m[blockIdx.y] * BM;
    const int n0   = blockIdx.x * BN;
    const float* Bp = w_proj + (size_t)e * H_DIM * I_DIM;

    __shared__ float As[BM][BK + 1];
    __shared__ float Bs[BN][BK + 1];
    __shared__ int   toks[BM];
    __shared__ float sgate[BM];

    const int tid = threadIdx.x;
    if (tid < BM) {
        int r = row0 + tid;
        int rr = (r < ne ? r : 0);
        toks[tid]  = g_tok[base + rr];
        sgate[tid] = g_gate[base + rr];
    }
    __syncthreads();

    const int arow = tid >> 2;
    const int acol = (tid & 3) * 4;
    const int ty = tid >> 4, tx = tid & 15;
    int rA = row0 + arow; rA = (rA < ne ? rA : 0);
    const size_t a_base = (size_t)(base + rA) * I_DIM + acol;
    const size_t b_base = (size_t)(n0 + arow) * I_DIM + acol;

    float acc[4][4];
#pragma unroll
    for (int i = 0; i < 4; i++)
#pragma unroll
        for (int j = 0; j < 4; j++) acc[i][j] = 0.f;

    for (int k0 = 0; k0 < I_DIM; k0 += BK) {
        float4 av = *(const float4*)(g_hbuf + a_base + k0);
        float4 bv = *(const float4*)(Bp     + b_base + k0);
        As[arow][acol] = av.x; As[arow][acol + 1] = av.y;
        As[arow][acol + 2] = av.z; As[arow][acol + 3] = av.w;
        Bs[arow][acol] = bv.x; Bs[arow][acol + 1] = bv.y;
        Bs[arow][acol + 2] = bv.z; Bs[arow][acol + 3] = bv.w;
        __syncthreads();
#pragma unroll
        for (int kk = 0; kk < BK; kk++) {
            float a[4], b[4];
#pragma unroll
            for (int i = 0; i < 4; i++) a[i] = As[ty * 4 + i][kk];
#pragma unroll
            for (int j = 0; j < 4; j++) b[j] = Bs[tx * 4 + j][kk];
#pragma unroll
            for (int i = 0; i < 4; i++)
#pragma unroll
                for (int j = 0; j < 4; j++) acc[i][j] += a[i] * b[j];
        }
        __syncthreads();
    }

#pragma unroll
    for (int i = 0; i < 4; i++) {
        int r = row0 + ty * 4 + i;
        if (r < ne) {
            int   tok = toks[ty * 4 + i];
            float g   = sgate[ty * 4 + i];
#pragma unroll
            for (int j = 0; j < 4; j++) {
                int c = n0 + tx * 4 + j;
                float v = acc[i][j] + b_proj[e * H_DIM + c];
                atomicAdd(out + (size_t)tok * H_DIM + c, g * v);
            }
        }
    }
}

// ---------------- aux loss ----------------
__global__ void aux_kernel(float* __restrict__ out) {
    float sumA = 0.f, sumF = 0.f;
    for (int e = 0; e < N_EXP; e++) {
        sumA += fabsf(g_accp[e]);
        sumF += fabsf((float)g_counts[e]);
    }
    float sw = 0.f;
    for (int e = 0; e < N_EXP; e++)
        sw += (g_accp[e] / sumA) * ((float)g_counts[e] / sumF);
    sw *= (float)N_EXP;
    float z = g_zsum / (float)T_TOKENS;
    out[AUX_OFF] = sw + 0.1f * z;
}

// ---------------- launch ----------------
extern "C" void kernel_launch(void* const* d_in, const int* in_sizes, int n_in,
                              void* d_out, int out_size) {
    const float* x      = (const float*)d_in[0];
    const float* wg     = (const float*)d_in[1];
    const float* w_fc   = (const float*)d_in[2];
    const float* b_fc   = (const float*)d_in[3];
    const float* w_proj = (const float*)d_in[4];
    const float* b_proj = (const float*)d_in[5];
    float* out = (float*)d_out;

    cudaMemsetAsync(out, 0, (size_t)OUT_ELEMS * sizeof(float), 0);
    init_kernel<<<1, 32>>>();
    router_kernel<<<T_TOKENS, 128>>>(x, wg, out);
    build_kernel<<<1, 1>>>();
    scatter_kernel<<<T_TOKENS / 128, 128>>>();
    gemm1_kernel<<<dim3(I_DIM / BN, MAXTILES), 256>>>(x, w_fc, b_fc);
    gemm2_kernel<<<dim3(H_DIM / BN, MAXTILES), 256>>>(w_proj, b_proj, out);
    aux_kernel<<<1, 1>>>(out);
}

// round 4
// speedup vs baseline: 3.3148x; 3.1437x over previous
#include <cuda_runtime.h>
#include <math.h>

// Problem constants (fixed by setup_inputs)
#define T_TOKENS 4096
#define H_DIM    1024
#define I_DIM    4096
#define N_EXP    8
#define TOPK     2
#define OUT_ELEMS  (T_TOKENS * H_DIM)            // 4,194,304
#define LOGITS_OFF OUT_ELEMS                     // router_logits [T, E]
#define AUX_OFF    (OUT_ELEMS + T_TOKENS * N_EXP)// aux_loss scalar
#define MAXROWS  (T_TOKENS * TOPK)               // 8192 dispatched rows

#define BM 128
#define BN 128
#define BK 16
#define SKA 20          // padded smem row stride (floats): conflict-free for frag loads
#define MAXTILES 72     // worst case sum_e ceil(ne/128) <= 64 + 8

// ---------------- device scratch (no allocation allowed) ----------------
__device__ float g_hbuf[(size_t)(MAXROWS + BM) * I_DIM];   // padded intermediate h
__device__ int   g_counts[N_EXP];
__device__ int   g_offsets[N_EXP];
__device__ int   g_cursor[N_EXP];
__device__ int   g_tok[MAXROWS];
__device__ float g_gate[MAXROWS];
__device__ int   g_top_idx[T_TOKENS * TOPK];
__device__ float g_top_gate[T_TOKENS * TOPK];
__device__ float g_accp[N_EXP];
__device__ float g_zsum;
__device__ int   g_tile_e[MAXTILES];
__device__ int   g_tile_m[MAXTILES];

// ---------------- helpers ----------------
__device__ __forceinline__ unsigned f2tf32(float f) {
    unsigned u;
    asm("cvt.rna.tf32.f32 %0, %1;" : "=r"(u) : "f"(f));
    return u;
}

#define MMA_TF32(d, a, b)                                                     \
    asm volatile("mma.sync.aligned.m16n8k8.row.col.f32.tf32.tf32.f32 "        \
                 "{%0,%1,%2,%3}, {%4,%5,%6,%7}, {%8,%9}, {%0,%1,%2,%3};"      \
                 : "+f"(d[0]), "+f"(d[1]), "+f"(d[2]), "+f"(d[3])             \
                 : "r"(a[0]), "r"(a[1]), "r"(a[2]), "r"(a[3]),                \
                   "r"(b[0]), "r"(b[1]))

// ---------------- init ----------------
__global__ void init_kernel() {
    int i = threadIdx.x;
    if (i < N_EXP) {
        g_counts[i] = 0;
        g_cursor[i] = 0;
        g_accp[i]   = 0.f;
    }
    if (i == 0) g_zsum = 0.f;
}

// ---------------- router: logits, top-2 gates, aux stats ----------------
__global__ void router_kernel(const float* __restrict__ x,
                              const float* __restrict__ wg,
                              float* __restrict__ out) {
    __shared__ float sl[N_EXP];
    const int t   = blockIdx.x;
    const int tid = threadIdx.x;
    if (tid < N_EXP) sl[tid] = 0.f;
    __syncthreads();

    float p[N_EXP];
#pragma unroll
    for (int e = 0; e < N_EXP; e++) p[e] = 0.f;

    const float* xr = x + (size_t)t * H_DIM;
    for (int h = tid; h < H_DIM; h += blockDim.x) {
        float xv = xr[h];
#pragma unroll
        for (int e = 0; e < N_EXP; e++) p[e] += xv * wg[h * N_EXP + e];
    }
#pragma unroll
    for (int off = 16; off > 0; off >>= 1) {
#pragma unroll
        for (int e = 0; e < N_EXP; e++)
            p[e] += __shfl_down_sync(0xffffffffu, p[e], off);
    }
    if ((tid & 31) == 0) {
#pragma unroll
        for (int e = 0; e < N_EXP; e++) atomicAdd(&sl[e], p[e]);
    }
    __syncthreads();

    if (tid == 0) {
        float l[N_EXP];
#pragma unroll
        for (int e = 0; e < N_EXP; e++) {
            l[e] = sl[e];
            out[LOGITS_OFF + t * N_EXP + e] = l[e];
        }
        int i0 = 0; float v0 = l[0];
#pragma unroll
        for (int e = 1; e < N_EXP; e++) if (l[e] > v0) { v0 = l[e]; i0 = e; }
        int i1 = -1; float v1 = -1e30f;
#pragma unroll
        for (int e = 0; e < N_EXP; e++) if (e != i0 && l[e] > v1) { v1 = l[e]; i1 = e; }
        float g0 = 1.f / (1.f + expf(v1 - v0));
        float g1 = 1.f - g0;
        g_top_idx[2 * t]      = i0;  g_top_gate[2 * t]      = g0;
        g_top_idx[2 * t + 1]  = i1;  g_top_gate[2 * t + 1]  = g1;
        atomicAdd(&g_counts[i0], 1);
        atomicAdd(&g_counts[i1], 1);
        float m = l[0];
#pragma unroll
        for (int e = 1; e < N_EXP; e++) m = fmaxf(m, l[e]);
        float den = 0.f;
#pragma unroll
        for (int e = 0; e < N_EXP; e++) den += expf(l[e] - m);
#pragma unroll
        for (int e = 0; e < N_EXP; e++) atomicAdd(&g_accp[e], expf(l[e] - m) / den);
        float lse = m + logf(den);
        atomicAdd(&g_zsum, lse * lse);
    }
}

// ---------------- offsets + tile worklist ----------------
__global__ void build_kernel() {
    int off = 0;
    for (int e = 0; e < N_EXP; e++) { g_offsets[e] = off; off += g_counts[e]; }
    int gm = 0;
    for (int e = 0; e < N_EXP; e++) {
        int nt = (g_counts[e] + BM - 1) / BM;
        for (int i = 0; i < nt && gm < MAXTILES; i++) {
            g_tile_e[gm] = e; g_tile_m[gm] = i; gm++;
        }
    }
    for (; gm < MAXTILES; gm++) g_tile_e[gm] = -1;
}

// ---------------- scatter tokens into per-expert groups ----------------
__global__ void scatter_kernel() {
    int t = blockIdx.x * blockDim.x + threadIdx.x;
    if (t >= T_TOKENS) return;
#pragma unroll
    for (int k = 0; k < TOPK; k++) {
        int e   = g_top_idx[2 * t + k];
        int pos = atomicAdd(&g_cursor[e], 1);
        int idx = g_offsets[e] + pos;
        g_tok[idx]  = t;
        g_gate[idx] = g_top_gate[2 * t + k];
    }
}

// ---------------- GEMM1 (tf32 tensor cores): h = gelu(x_g @ w_fc[e]^T + b) ----
__global__ __launch_bounds__(256) void gemm1_kernel(const float* __restrict__ x,
                                                    const float* __restrict__ w_fc,
                                                    const float* __restrict__ b_fc) {
    const int e = g_tile_e[blockIdx.y];
    if (e < 0) return;
    const int ne   = g_counts[e];
    const int base = g_offsets[e];
    const int row0 = g_tile_m[blockIdx.y] * BM;
    const int n0   = blockIdx.x * BN;
    const float* Bp = w_fc + (size_t)e * I_DIM * H_DIM;

    __shared__ float As[2][BM * SKA];
    __shared__ float Bs[2][BN * SKA];
    __shared__ int   toks[BM];

    const int tid  = threadIdx.x;
    const int lane = tid & 31;
    const int wid  = tid >> 5;
    const int wm   = wid & 1;        // 2 m-warps
    const int wn   = wid >> 1;       // 4 n-warps
    const int g    = lane >> 2;
    const int tg   = lane & 3;

    if (tid < BM) {
        int r = row0 + tid;
        toks[tid] = g_tok[base + (r < ne ? r : 0)];
    }
    __syncthreads();

    const int ldr = tid >> 2;        // 0..63
    const int ldq = (tid & 3) * 4;   // 0,4,8,12
    const float* a0p = x + (size_t)toks[ldr]      * H_DIM + ldq;
    const float* a1p = x + (size_t)toks[ldr + 64] * H_DIM + ldq;
    const float* b0p = Bp + (size_t)(n0 + ldr)      * H_DIM + ldq;
    const float* b1p = Bp + (size_t)(n0 + ldr + 64) * H_DIM + ldq;

    float4 ra0, ra1, rb0, rb1;
    float acc[4][4][4];
#pragma unroll
    for (int mt = 0; mt < 4; mt++)
#pragma unroll
        for (int nt = 0; nt < 4; nt++)
#pragma unroll
            for (int k = 0; k < 4; k++) acc[mt][nt][k] = 0.f;

    // prologue: load + store tile 0
    ra0 = *(const float4*)(a0p); ra1 = *(const float4*)(a1p);
    rb0 = *(const float4*)(b0p); rb1 = *(const float4*)(b1p);
    {
        float* A = As[0]; float* B = Bs[0];
        A[ldr * SKA + ldq + 0] = __uint_as_float(f2tf32(ra0.x));
        A[ldr * SKA + ldq + 1] = __uint_as_float(f2tf32(ra0.y));
        A[ldr * SKA + ldq + 2] = __uint_as_float(f2tf32(ra0.z));
        A[ldr * SKA + ldq + 3] = __uint_as_float(f2tf32(ra0.w));
        A[(ldr + 64) * SKA + ldq + 0] = __uint_as_float(f2tf32(ra1.x));
        A[(ldr + 64) * SKA + ldq + 1] = __uint_as_float(f2tf32(ra1.y));
        A[(ldr + 64) * SKA + ldq + 2] = __uint_as_float(f2tf32(ra1.z));
        A[(ldr + 64) * SKA + ldq + 3] = __uint_as_float(f2tf32(ra1.w));
        B[ldr * SKA + ldq + 0] = __uint_as_float(f2tf32(rb0.x));
        B[ldr * SKA + ldq + 1] = __uint_as_float(f2tf32(rb0.y));
        B[ldr * SKA + ldq + 2] = __uint_as_float(f2tf32(rb0.z));
        B[ldr * SKA + ldq + 3] = __uint_as_float(f2tf32(rb0.w));
        B[(ldr + 64) * SKA + ldq + 0] = __uint_as_float(f2tf32(rb1.x));
        B[(ldr + 64) * SKA + ldq + 1] = __uint_as_float(f2tf32(rb1.y));
        B[(ldr + 64) * SKA + ldq + 2] = __uint_as_float(f2tf32(rb1.z));
        B[(ldr + 64) * SKA + ldq + 3] = __uint_as_float(f2tf32(rb1.w));
    }
    __syncthreads();

    const int nIter = H_DIM / BK;    // 64
    for (int it = 0; it < nIter; it++) {
        const int buf = it & 1;
        if (it + 1 < nIter) {
            int k0 = (it + 1) * BK;
            ra0 = *(const float4*)(a0p + k0); ra1 = *(const float4*)(a1p + k0);
            rb0 = *(const float4*)(b0p + k0); rb1 = *(const float4*)(b1p + k0);
        }
        const float* Abuf = As[buf];
        const float* Bbuf = Bs[buf];
#pragma unroll
        for (int kk = 0; kk < BK; kk += 8) {
            unsigned a[4][4], b[4][2];
#pragma unroll
            for (int mt = 0; mt < 4; mt++) {
                const float* p = Abuf + (wm * 64 + mt * 16 + g) * SKA + kk + tg;
                a[mt][0] = __float_as_uint(p[0]);
                a[mt][1] = __float_as_uint(p[8 * SKA]);
                a[mt][2] = __float_as_uint(p[4]);
                a[mt][3] = __float_as_uint(p[8 * SKA + 4]);
            }
#pragma unroll
            for (int nt = 0; nt < 4; nt++) {
                const float* p = Bbuf + (wn * 32 + nt * 8 + g) * SKA + kk + tg;
                b[nt][0] = __float_as_uint(p[0]);
                b[nt][1] = __float_as_uint(p[4]);
            }
#pragma unroll
            for (int mt = 0; mt < 4; mt++)
#pragma unroll
                for (int nt = 0; nt < 4; nt++)
                    MMA_TF32(acc[mt][nt], a[mt], b[nt]);
        }
        if (it + 1 < nIter) {
            float* A = As[buf ^ 1]; float* B = Bs[buf ^ 1];
            A[ldr * SKA + ldq + 0] = __uint_as_float(f2tf32(ra0.x));
            A[ldr * SKA + ldq + 1] = __uint_as_float(f2tf32(ra0.y));
            A[ldr * SKA + ldq + 2] = __uint_as_float(f2tf32(ra0.z));
            A[ldr * SKA + ldq + 3] = __uint_as_float(f2tf32(ra0.w));
            A[(ldr + 64) * SKA + ldq + 0] = __uint_as_float(f2tf32(ra1.x));
            A[(ldr + 64) * SKA + ldq + 1] = __uint_as_float(f2tf32(ra1.y));
            A[(ldr + 64) * SKA + ldq + 2] = __uint_as_float(f2tf32(ra1.z));
            A[(ldr + 64) * SKA + ldq + 3] = __uint_as_float(f2tf32(ra1.w));
            B[ldr * SKA + ldq + 0] = __uint_as_float(f2tf32(rb0.x));
            B[ldr * SKA + ldq + 1] = __uint_as_float(f2tf32(rb0.y));
            B[ldr * SKA + ldq + 2] = __uint_as_float(f2tf32(rb0.z));
            B[ldr * SKA + ldq + 3] = __uint_as_float(f2tf32(rb0.w));
            B[(ldr + 64) * SKA + ldq + 0] = __uint_as_float(f2tf32(rb1.x));
            B[(ldr + 64) * SKA + ldq + 1] = __uint_as_float(f2tf32(rb1.y));
            B[(ldr + 64) * SKA + ldq + 2] = __uint_as_float(f2tf32(rb1.z));
            B[(ldr + 64) * SKA + ldq + 3] = __uint_as_float(f2tf32(rb1.w));
        }
        __syncthreads();
    }

    // epilogue: bias + gelu -> g_hbuf
#pragma unroll
    for (int mt = 0; mt < 4; mt++) {
#pragma unroll
        for (int i = 0; i < 2; i++) {
            int lm = wm * 64 + mt * 16 + g + i * 8;
            int r  = row0 + lm;
            if (r < ne) {
                size_t hrow = (size_t)(base + r) * I_DIM;
#pragma unroll
                for (int nt = 0; nt < 4; nt++) {
                    int c = n0 + wn * 32 + nt * 8 + tg * 2;
                    float v0 = acc[mt][nt][i * 2 + 0] + b_fc[e * I_DIM + c];
                    float v1 = acc[mt][nt][i * 2 + 1] + b_fc[e * I_DIM + c + 1];
                    v0 = 0.5f * v0 * (1.0f + erff(v0 * 0.7071067811865476f));
                    v1 = 0.5f * v1 * (1.0f + erff(v1 * 0.7071067811865476f));
                    g_hbuf[hrow + c]     = v0;
                    g_hbuf[hrow + c + 1] = v1;
                }
            }
        }
    }
}

// ---------------- GEMM2 (tf32): out += gate * (h @ w_proj[e]^T + b) ----------------
__global__ __launch_bounds__(256) void gemm2_kernel(const float* __restrict__ w_proj,
                                                    const float* __restrict__ b_proj,
                                                    float* __restrict__ out) {
    const int e = g_tile_e[blockIdx.y];
    if (e < 0) return;
    const int ne   = g_counts[e];
    const int base = g_offsets[e];
    const int row0 = g_tile_m[blockIdx.y] * BM;
    const int n0   = blockIdx.x * BN;
    const float* Bp = w_proj + (size_t)e * H_DIM * I_DIM;

    __shared__ float As[2][BM * SKA];
    __shared__ float Bs[2][BN * SKA];
    __shared__ int   toks[BM];
    __shared__ float sgate[BM];

    const int tid  = threadIdx.x;
    const int lane = tid & 31;
    const int wid  = tid >> 5;
    const int wm   = wid & 1;
    const int wn   = wid >> 1;
    const int g    = lane >> 2;
    const int tg   = lane & 3;

    if (tid < BM) {
        int r  = row0 + tid;
        int rr = (r < ne ? r : 0);
        toks[tid]  = g_tok[base + rr];
        sgate[tid] = g_gate[base + rr];
    }

    const int ldr = tid >> 2;
    const int ldq = (tid & 3) * 4;
    const float* a0p = g_hbuf + (size_t)(base + row0 + ldr)      * I_DIM + ldq;
    const float* a1p = g_hbuf + (size_t)(base + row0 + ldr + 64) * I_DIM + ldq;
    const float* b0p = Bp + (size_t)(n0 + ldr)      * I_DIM + ldq;
    const float* b1p = Bp + (size_t)(n0 + ldr + 64) * I_DIM + ldq;

    float4 ra0, ra1, rb0, rb1;
    float acc[4][4][4];
#pragma unroll
    for (int mt = 0; mt < 4; mt++)
#pragma unroll
        for (int nt = 0; nt < 4; nt++)
#pragma unroll
            for (int k = 0; k < 4; k++) acc[mt][nt][k] = 0.f;

    ra0 = *(const float4*)(a0p); ra1 = *(const float4*)(a1p);
    rb0 = *(const float4*)(b0p); rb1 = *(const float4*)(b1p);
    {
        float* A = As[0]; float* B = Bs[0];
        A[ldr * SKA + ldq + 0] = __uint_as_float(f2tf32(ra0.x));
        A[ldr * SKA + ldq + 1] = __uint_as_float(f2tf32(ra0.y));
        A[ldr * SKA + ldq + 2] = __uint_as_float(f2tf32(ra0.z));
        A[ldr * SKA + ldq + 3] = __uint_as_float(f2tf32(ra0.w));
        A[(ldr + 64) * SKA + ldq + 0] = __uint_as_float(f2tf32(ra1.x));
        A[(ldr + 64) * SKA + ldq + 1] = __uint_as_float(f2tf32(ra1.y));
        A[(ldr + 64) * SKA + ldq + 2] = __uint_as_float(f2tf32(ra1.z));
        A[(ldr + 64) * SKA + ldq + 3] = __uint_as_float(f2tf32(ra1.w));
        B[ldr * SKA + ldq + 0] = __uint_as_float(f2tf32(rb0.x));
        B[ldr * SKA + ldq + 1] = __uint_as_float(f2tf32(rb0.y));
        B[ldr * SKA + ldq + 2] = __uint_as_float(f2tf32(rb0.z));
        B[ldr * SKA + ldq + 3] = __uint_as_float(f2tf32(rb0.w));
        B[(ldr + 64) * SKA + ldq + 0] = __uint_as_float(f2tf32(rb1.x));
        B[(ldr + 64) * SKA + ldq + 1] = __uint_as_float(f2tf32(rb1.y));
        B[(ldr + 64) * SKA + ldq + 2] = __uint_as_float(f2tf32(rb1.z));
        B[(ldr + 64) * SKA + ldq + 3] = __uint_as_float(f2tf32(rb1.w));
    }
    __syncthreads();

    const int nIter = I_DIM / BK;    // 256
    for (int it = 0; it < nIter; it++) {
        const int buf = it & 1;
        if (it + 1 < nIter) {
            int k0 = (it + 1) * BK;
            ra0 = *(const float4*)(a0p + k0); ra1 = *(const float4*)(a1p + k0);
            rb0 = *(const float4*)(b0p + k0); rb1 = *(const float4*)(b1p + k0);
        }
        const float* Abuf = As[buf];
        const float* Bbuf = Bs[buf];
#pragma unroll
        for (int kk = 0; kk < BK; kk += 8) {
            unsigned a[4][4], b[4][2];
#pragma unroll
            for (int mt = 0; mt < 4; mt++) {
                const float* p = Abuf + (wm * 64 + mt * 16 + g) * SKA + kk + tg;
                a[mt][0] = __float_as_uint(p[0]);
                a[mt][1] = __float_as_uint(p[8 * SKA]);
                a[mt][2] = __float_as_uint(p[4]);
                a[mt][3] = __float_as_uint(p[8 * SKA + 4]);
            }
#pragma unroll
            for (int nt = 0; nt < 4; nt++) {
                const float* p = Bbuf + (wn * 32 + nt * 8 + g) * SKA + kk + tg;
                b[nt][0] = __float_as_uint(p[0]);
                b[nt][1] = __float_as_uint(p[4]);
            }
#pragma unroll
            for (int mt = 0; mt < 4; mt++)
#pragma unroll
                for (int nt = 0; nt < 4; nt++)
                    MMA_TF32(acc[mt][nt], a[mt], b[nt]);
        }
        if (it + 1 < nIter) {
            float* A = As[buf ^ 1]; float* B = Bs[buf ^ 1];
            A[ldr * SKA + ldq + 0] = __uint_as_float(f2tf32(ra0.x));
            A[ldr * SKA + ldq + 1] = __uint_as_float(f2tf32(ra0.y));
            A[ldr * SKA + ldq + 2] = __uint_as_float(f2tf32(ra0.z));
            A[ldr * SKA + ldq + 3] = __uint_as_float(f2tf32(ra0.w));
            A[(ldr + 64) * SKA + ldq + 0] = __uint_as_float(f2tf32(ra1.x));
            A[(ldr + 64) * SKA + ldq + 1] = __uint_as_float(f2tf32(ra1.y));
            A[(ldr + 64) * SKA + ldq + 2] = __uint_as_float(f2tf32(ra1.z));
            A[(ldr + 64) * SKA + ldq + 3] = __uint_as_float(f2tf32(ra1.w));
            B[ldr * SKA + ldq + 0] = __uint_as_float(f2tf32(rb0.x));
            B[ldr * SKA + ldq + 1] = __uint_as_float(f2tf32(rb0.y));
            B[ldr * SKA + ldq + 2] = __uint_as_float(f2tf32(rb0.z));
            B[ldr * SKA + ldq + 3] = __uint_as_float(f2tf32(rb0.w));
            B[(ldr + 64) * SKA + ldq + 0] = __uint_as_float(f2tf32(rb1.x));
            B[(ldr + 64) * SKA + ldq + 1] = __uint_as_float(f2tf32(rb1.y));
            B[(ldr + 64) * SKA + ldq + 2] = __uint_as_float(f2tf32(rb1.z));
            B[(ldr + 64) * SKA + ldq + 3] = __uint_as_float(f2tf32(rb1.w));
        }
        __syncthreads();
    }

    // epilogue: bias, gate, atomic combine into out
#pragma unroll
    for (int mt = 0; mt < 4; mt++) {
#pragma unroll
        for (int i = 0; i < 2; i++) {
            int lm = wm * 64 + mt * 16 + g + i * 8;
            int r  = row0 + lm;
            if (r < ne) {
                int   tok = toks[lm];
                float gt  = sgate[lm];
                float* orow = out + (size_t)tok * H_DIM;
#pragma unroll
                for (int nt = 0; nt < 4; nt++) {
                    int c = n0 + wn * 32 + nt * 8 + tg * 2;
                    float v0 = acc[mt][nt][i * 2 + 0] + b_proj[e * H_DIM + c];
                    float v1 = acc[mt][nt][i * 2 + 1] + b_proj[e * H_DIM + c + 1];
                    atomicAdd(orow + c,     gt * v0);
                    atomicAdd(orow + c + 1, gt * v1);
                }
            }
        }
    }
}

// ---------------- aux loss ----------------
__global__ void aux_kernel(float* __restrict__ out) {
    float sumA = 0.f, sumF = 0.f;
    for (int e = 0; e < N_EXP; e++) {
        sumA += fabsf(g_accp[e]);
        sumF += fabsf((float)g_counts[e]);
    }
    float sw = 0.f;
    for (int e = 0; e < N_EXP; e++)
        sw += (g_accp[e] / sumA) * ((float)g_counts[e] / sumF);
    sw *= (float)N_EXP;
    float z = g_zsum / (float)T_TOKENS;
    out[AUX_OFF] = sw + 0.1f * z;
}

// ---------------- launch ----------------
extern "C" void kernel_launch(void* const* d_in, const int* in_sizes, int n_in,
                              void* d_out, int out_size) {
    const float* x      = (const float*)d_in[0];
    const float* wg     = (const float*)d_in[1];
    const float* w_fc   = (const float*)d_in[2];
    const float* b_fc   = (const float*)d_in[3];
    const float* w_proj = (const float*)d_in[4];
    const float* b_proj = (const float*)d_in[5];
    float* out = (float*)d_out;

    cudaMemsetAsync(out, 0, (size_t)OUT_ELEMS * sizeof(float), 0);
    init_kernel<<<1, 32>>>();
    router_kernel<<<T_TOKENS, 128>>>(x, wg, out);
    build_kernel<<<1, 1>>>();
    scatter_kernel<<<T_TOKENS / 128, 128>>>();
    gemm1_kernel<<<dim3(I_DIM / BN, MAXTILES), 256>>>(x, w_fc, b_fc);
    gemm2_kernel<<<dim3(H_DIM / BN, MAXTILES), 256>>>(w_proj, b_proj, out);
    aux_kernel<<<1, 1>>>(out);
}

// round 5
// speedup vs baseline: 3.6349x; 1.0966x over previous
#include <cuda_runtime.h>
#include <math.h>

// Problem constants (fixed by setup_inputs)
#define T_TOKENS 4096
#define H_DIM    1024
#define I_DIM    4096
#define N_EXP    8
#define TOPK     2
#define OUT_ELEMS  (T_TOKENS * H_DIM)            // 4,194,304
#define LOGITS_OFF OUT_ELEMS                     // router_logits [T, E]
#define AUX_OFF    (OUT_ELEMS + T_TOKENS * N_EXP)// aux_loss scalar
#define MAXROWS  (T_TOKENS * TOPK)               // 8192 dispatched rows

#define BM 128
#define BN 128
#define BK 16
#define SKA 20          // padded smem row stride (floats); 80B = 5*16B -> cp.async-aligned
#define STAGES 4
#define STAGE_F (BM * SKA)                       // floats per matrix per stage
#define SMEM_BYTES (STAGES * 2 * STAGE_F * 4 + BM * 8)
#define MAXTILES 72     // worst case sum_e ceil(ne/128) <= 64 + 8

// ---------------- device scratch (no allocation allowed) ----------------
__device__ float g_hbuf[(size_t)(MAXROWS + BM) * I_DIM];   // padded intermediate h
__device__ int   g_counts[N_EXP];
__device__ int   g_offsets[N_EXP];
__device__ int   g_cursor[N_EXP];
__device__ int   g_tok[MAXROWS];
__device__ float g_gate[MAXROWS];
__device__ int   g_top_idx[T_TOKENS * TOPK];
__device__ float g_top_gate[T_TOKENS * TOPK];
__device__ float g_accp[N_EXP];
__device__ float g_zsum;
__device__ int   g_tile_e[MAXTILES];
__device__ int   g_tile_m[MAXTILES];

// ---------------- helpers ----------------
__device__ __forceinline__ unsigned f2tf32(float f) {
    unsigned u;
    asm("cvt.rna.tf32.f32 %0, %1;" : "=r"(u) : "f"(f));
    return u;
}

#define MMA_TF32(d, a, b)                                                     \
    asm volatile("mma.sync.aligned.m16n8k8.row.col.f32.tf32.tf32.f32 "        \
                 "{%0,%1,%2,%3}, {%4,%5,%6,%7}, {%8,%9}, {%0,%1,%2,%3};"      \
                 : "+f"(d[0]), "+f"(d[1]), "+f"(d[2]), "+f"(d[3])             \
                 : "r"(a[0]), "r"(a[1]), "r"(a[2]), "r"(a[3]),                \
                   "r"(b[0]), "r"(b[1]))

#define CP_ASYNC16(dst, src)                                                  \
    asm volatile("cp.async.cg.shared.global [%0], [%1], 16;"                  \
                 :: "r"(dst), "l"(src))
#define CP_COMMIT() asm volatile("cp.async.commit_group;")
#define CP_WAIT2()  asm volatile("cp.async.wait_group %0;" :: "n"(STAGES - 2))
#define CP_WAIT0()  asm volatile("cp.async.wait_group 0;")

__device__ __forceinline__ unsigned smem_u32(const void* p) {
    return (unsigned)__cvta_generic_to_shared(p);
}

// ---------------- init ----------------
__global__ void init_kernel() {
    int i = threadIdx.x;
    if (i < N_EXP) {
        g_counts[i] = 0;
        g_cursor[i] = 0;
        g_accp[i]   = 0.f;
    }
    if (i == 0) g_zsum = 0.f;
}

// ---------------- router: logits, top-2 gates, aux stats ----------------
__global__ void router_kernel(const float* __restrict__ x,
                              const float* __restrict__ wg,
                              float* __restrict__ out) {
    __shared__ float sl[N_EXP];
    const int t   = blockIdx.x;
    const int tid = threadIdx.x;
    if (tid < N_EXP) sl[tid] = 0.f;
    __syncthreads();

    float p[N_EXP];
#pragma unroll
    for (int e = 0; e < N_EXP; e++) p[e] = 0.f;

    const float* xr = x + (size_t)t * H_DIM;
    for (int h = tid; h < H_DIM; h += blockDim.x) {
        float xv = xr[h];
#pragma unroll
        for (int e = 0; e < N_EXP; e++) p[e] += xv * wg[h * N_EXP + e];
    }
#pragma unroll
    for (int off = 16; off > 0; off >>= 1) {
#pragma unroll
        for (int e = 0; e < N_EXP; e++)
            p[e] += __shfl_down_sync(0xffffffffu, p[e], off);
    }
    if ((tid & 31) == 0) {
#pragma unroll
        for (int e = 0; e < N_EXP; e++) atomicAdd(&sl[e], p[e]);
    }
    __syncthreads();

    if (tid == 0) {
        float l[N_EXP];
#pragma unroll
        for (int e = 0; e < N_EXP; e++) {
            l[e] = sl[e];
            out[LOGITS_OFF + t * N_EXP + e] = l[e];
        }
        int i0 = 0; float v0 = l[0];
#pragma unroll
        for (int e = 1; e < N_EXP; e++) if (l[e] > v0) { v0 = l[e]; i0 = e; }
        int i1 = -1; float v1 = -1e30f;
#pragma unroll
        for (int e = 0; e < N_EXP; e++) if (e != i0 && l[e] > v1) { v1 = l[e]; i1 = e; }
        float g0 = 1.f / (1.f + expf(v1 - v0));
        float g1 = 1.f - g0;
        g_top_idx[2 * t]      = i0;  g_top_gate[2 * t]      = g0;
        g_top_idx[2 * t + 1]  = i1;  g_top_gate[2 * t + 1]  = g1;
        atomicAdd(&g_counts[i0], 1);
        atomicAdd(&g_counts[i1], 1);
        float m = l[0];
#pragma unroll
        for (int e = 1; e < N_EXP; e++) m = fmaxf(m, l[e]);
        float den = 0.f;
#pragma unroll
        for (int e = 0; e < N_EXP; e++) den += expf(l[e] - m);
#pragma unroll
        for (int e = 0; e < N_EXP; e++) atomicAdd(&g_accp[e], expf(l[e] - m) / den);
        float lse = m + logf(den);
        atomicAdd(&g_zsum, lse * lse);
    }
}

// ---------------- offsets + tile worklist ----------------
__global__ void build_kernel() {
    int off = 0;
    for (int e = 0; e < N_EXP; e++) { g_offsets[e] = off; off += g_counts[e]; }
    int gm = 0;
    for (int e = 0; e < N_EXP; e++) {
        int nt = (g_counts[e] + BM - 1) / BM;
        for (int i = 0; i < nt && gm < MAXTILES; i++) {
            g_tile_e[gm] = e; g_tile_m[gm] = i; gm++;
        }
    }
    for (; gm < MAXTILES; gm++) g_tile_e[gm] = -1;
}

// ---------------- scatter tokens into per-expert groups ----------------
__global__ void scatter_kernel() {
    int t = blockIdx.x * blockDim.x + threadIdx.x;
    if (t >= T_TOKENS) return;
#pragma unroll
    for (int k = 0; k < TOPK; k++) {
        int e   = g_top_idx[2 * t + k];
        int pos = atomicAdd(&g_cursor[e], 1);
        int idx = g_offsets[e] + pos;
        g_tok[idx]  = t;
        g_gate[idx] = g_top_gate[2 * t + k];
    }
}

// ---- shared GEMM body pieces (identical fragment mapping to the passing R4 kernel) ----

// Issue one pipeline stage: 2 A chunks + 2 B chunks of 16B per thread.
#define ISSUE_STAGE(sidx, k0)                                                 \
    do {                                                                      \
        unsigned ad = aDstBase + (unsigned)(sidx) * (STAGE_F * 4);            \
        unsigned bd = bDstBase + (unsigned)(sidx) * (STAGE_F * 4);            \
        CP_ASYNC16(ad,                 a0p + (k0));                           \
        CP_ASYNC16(ad + 64 * SKA * 4,  a1p + (k0));                           \
        CP_ASYNC16(bd,                 b0p + (k0));                           \
        CP_ASYNC16(bd + 64 * SKA * 4,  b1p + (k0));                           \
    } while (0)

#define COMPUTE_STAGE(Abuf, Bbuf)                                             \
    do {                                                                      \
        _Pragma("unroll")                                                     \
        for (int kk = 0; kk < BK; kk += 8) {                                  \
            unsigned a[4][4], b[4][2];                                        \
            _Pragma("unroll")                                                 \
            for (int mt = 0; mt < 4; mt++) {                                  \
                const float* p = (Abuf) + (wm * 64 + mt * 16 + g) * SKA + kk + tg; \
                a[mt][0] = f2tf32(p[0]);                                      \
                a[mt][1] = f2tf32(p[8 * SKA]);                                \
                a[mt][2] = f2tf32(p[4]);                                      \
                a[mt][3] = f2tf32(p[8 * SKA + 4]);                            \
            }                                                                 \
            _Pragma("unroll")                                                 \
            for (int nt = 0; nt < 4; nt++) {                                  \
                const float* p = (Bbuf) + (wn * 32 + nt * 8 + g) * SKA + kk + tg; \
                b[nt][0] = f2tf32(p[0]);                                      \
                b[nt][1] = f2tf32(p[4]);                                      \
            }                                                                 \
            _Pragma("unroll")                                                 \
            for (int mt = 0; mt < 4; mt++)                                    \
                _Pragma("unroll")                                             \
                for (int nt = 0; nt < 4; nt++)                                \
                    MMA_TF32(acc[mt][nt], a[mt], b[nt]);                      \
        }                                                                     \
    } while (0)

// ---------------- GEMM1 (tf32, 4-stage cp.async): h = gelu(x_g @ w_fc[e]^T + b) ----
__global__ __launch_bounds__(256) void gemm1_kernel(const float* __restrict__ x,
                                                    const float* __restrict__ w_fc,
                                                    const float* __restrict__ b_fc) {
    const int e = g_tile_e[blockIdx.y];
    if (e < 0) return;
    const int ne   = g_counts[e];
    const int base = g_offsets[e];
    const int row0 = g_tile_m[blockIdx.y] * BM;
    const int n0   = blockIdx.x * BN;
    const float* Bp = w_fc + (size_t)e * I_DIM * H_DIM;

    extern __shared__ float smem[];
    float* As   = smem;                                // STAGES * STAGE_F
    float* Bs   = smem + STAGES * STAGE_F;             // STAGES * STAGE_F
    int*   toks = (int*)(smem + 2 * STAGES * STAGE_F);

    const int tid  = threadIdx.x;
    const int lane = tid & 31;
    const int wid  = tid >> 5;
    const int wm   = wid & 1;
    const int wn   = wid >> 1;
    const int g    = lane >> 2;
    const int tg   = lane & 3;

    if (tid < BM) {
        int r = row0 + tid;
        toks[tid] = g_tok[base + (r < ne ? r : 0)];
    }
    __syncthreads();

    const int ldr = tid >> 2;        // 0..63
    const int ldq = (tid & 3) * 4;   // 0,4,8,12
    const float* a0p = x + (size_t)toks[ldr]      * H_DIM + ldq;
    const float* a1p = x + (size_t)toks[ldr + 64] * H_DIM + ldq;
    const float* b0p = Bp + (size_t)(n0 + ldr)      * H_DIM + ldq;
    const float* b1p = Bp + (size_t)(n0 + ldr + 64) * H_DIM + ldq;

    const unsigned aDstBase = smem_u32(As) + (ldr * SKA + ldq) * 4;
    const unsigned bDstBase = smem_u32(Bs) + (ldr * SKA + ldq) * 4;

    float acc[4][4][4];
#pragma unroll
    for (int mt = 0; mt < 4; mt++)
#pragma unroll
        for (int nt = 0; nt < 4; nt++)
#pragma unroll
            for (int k = 0; k < 4; k++) acc[mt][nt][k] = 0.f;

    const int nIter = H_DIM / BK;    // 64
#pragma unroll
    for (int s = 0; s < STAGES - 1; s++) {
        ISSUE_STAGE(s, s * BK);
        CP_COMMIT();
    }

    for (int it = 0; it < nIter; it++) {
        CP_WAIT2();
        __syncthreads();
        int pf = it + STAGES - 1;
        if (pf < nIter) ISSUE_STAGE(pf % STAGES, pf * BK);
        CP_COMMIT();
        const float* Abuf = As + (it % STAGES) * STAGE_F;
        const float* Bbuf = Bs + (it % STAGES) * STAGE_F;
        COMPUTE_STAGE(Abuf, Bbuf);
    }
    CP_WAIT0();

    // epilogue: bias + gelu -> g_hbuf
#pragma unroll
    for (int mt = 0; mt < 4; mt++) {
#pragma unroll
        for (int i = 0; i < 2; i++) {
            int lm = wm * 64 + mt * 16 + g + i * 8;
            int r  = row0 + lm;
            if (r < ne) {
                size_t hrow = (size_t)(base + r) * I_DIM;
#pragma unroll
                for (int nt = 0; nt < 4; nt++) {
                    int c = n0 + wn * 32 + nt * 8 + tg * 2;
                    float v0 = acc[mt][nt][i * 2 + 0] + b_fc[e * I_DIM + c];
                    float v1 = acc[mt][nt][i * 2 + 1] + b_fc[e * I_DIM + c + 1];
                    v0 = 0.5f * v0 * (1.0f + erff(v0 * 0.7071067811865476f));
                    v1 = 0.5f * v1 * (1.0f + erff(v1 * 0.7071067811865476f));
                    g_hbuf[hrow + c]     = v0;
                    g_hbuf[hrow + c + 1] = v1;
                }
            }
        }
    }
}

// ---------------- GEMM2 (tf32, 4-stage cp.async): out += gate*(h @ w_proj^T + b) ----
__global__ __launch_bounds__(256) void gemm2_kernel(const float* __restrict__ w_proj,
                                                    const float* __restrict__ b_proj,
                                                    float* __restrict__ out) {
    const int e = g_tile_e[blockIdx.y];
    if (e < 0) return;
    const int ne   = g_counts[e];
    const int base = g_offsets[e];
    const int row0 = g_tile_m[blockIdx.y] * BM;
    const int n0   = blockIdx.x * BN;
    const float* Bp = w_proj + (size_t)e * H_DIM * I_DIM;

    extern __shared__ float smem[];
    float* As    = smem;
    float* Bs    = smem + STAGES * STAGE_F;
    int*   toks  = (int*)(smem + 2 * STAGES * STAGE_F);
    float* sgate = (float*)(toks + BM);

    const int tid  = threadIdx.x;
    const int lane = tid & 31;
    const int wid  = tid >> 5;
    const int wm   = wid & 1;
    const int wn   = wid >> 1;
    const int g    = lane >> 2;
    const int tg   = lane & 3;

    if (tid < BM) {
        int r  = row0 + tid;
        int rr = (r < ne ? r : 0);
        toks[tid]  = g_tok[base + rr];
        sgate[tid] = g_gate[base + rr];
    }

    const int ldr = tid >> 2;
    const int ldq = (tid & 3) * 4;
    const float* a0p = g_hbuf + (size_t)(base + row0 + ldr)      * I_DIM + ldq;
    const float* a1p = g_hbuf + (size_t)(base + row0 + ldr + 64) * I_DIM + ldq;
    const float* b0p = Bp + (size_t)(n0 + ldr)      * I_DIM + ldq;
    const float* b1p = Bp + (size_t)(n0 + ldr + 64) * I_DIM + ldq;

    const unsigned aDstBase = smem_u32(As) + (ldr * SKA + ldq) * 4;
    const unsigned bDstBase = smem_u32(Bs) + (ldr * SKA + ldq) * 4;

    float acc[4][4][4];
#pragma unroll
    for (int mt = 0; mt < 4; mt++)
#pragma unroll
        for (int nt = 0; nt < 4; nt++)
#pragma unroll
            for (int k = 0; k < 4; k++) acc[mt][nt][k] = 0.f;

    const int nIter = I_DIM / BK;    // 256
#pragma unroll
    for (int s = 0; s < STAGES - 1; s++) {
        ISSUE_STAGE(s, s * BK);
        CP_COMMIT();
    }

    for (int it = 0; it < nIter; it++) {
        CP_WAIT2();
        __syncthreads();
        int pf = it + STAGES - 1;
        if (pf < nIter) ISSUE_STAGE(pf % STAGES, pf * BK);
        CP_COMMIT();
        const float* Abuf = As + (it % STAGES) * STAGE_F;
        const float* Bbuf = Bs + (it % STAGES) * STAGE_F;
        COMPUTE_STAGE(Abuf, Bbuf);
    }
    CP_WAIT0();

    // epilogue: bias, gate, atomic combine into out
#pragma unroll
    for (int mt = 0; mt < 4; mt++) {
#pragma unroll
        for (int i = 0; i < 2; i++) {
            int lm = wm * 64 + mt * 16 + g + i * 8;
            int r  = row0 + lm;
            if (r < ne) {
                int   tok = toks[lm];
                float gt  = sgate[lm];
                float* orow = out + (size_t)tok * H_DIM;
#pragma unroll
                for (int nt = 0; nt < 4; nt++) {
                    int c = n0 + wn * 32 + nt * 8 + tg * 2;
                    float v0 = acc[mt][nt][i * 2 + 0] + b_proj[e * H_DIM + c];
                    float v1 = acc[mt][nt][i * 2 + 1] + b_proj[e * H_DIM + c + 1];
                    atomicAdd(orow + c,     gt * v0);
                    atomicAdd(orow + c + 1, gt * v1);
                }
            }
        }
    }
}

// ---------------- aux loss ----------------
__global__ void aux_kernel(float* __restrict__ out) {
    float sumA = 0.f, sumF = 0.f;
    for (int e = 0; e < N_EXP; e++) {
        sumA += fabsf(g_accp[e]);
        sumF += fabsf((float)g_counts[e]);
    }
    float sw = 0.f;
    for (int e = 0; e < N_EXP; e++)
        sw += (g_accp[e] / sumA) * ((float)g_counts[e] / sumF);
    sw *= (float)N_EXP;
    float z = g_zsum / (float)T_TOKENS;
    out[AUX_OFF] = sw + 0.1f * z;
}

// ---------------- launch ----------------
extern "C" void kernel_launch(void* const* d_in, const int* in_sizes, int n_in,
                              void* d_out, int out_size) {
    const float* x      = (const float*)d_in[0];
    const float* wg     = (const float*)d_in[1];
    const float* w_fc   = (const float*)d_in[2];
    const float* b_fc   = (const float*)d_in[3];
    const float* w_proj = (const float*)d_in[4];
    const float* b_proj = (const float*)d_in[5];
    float* out = (float*)d_out;

    static int configured = 0;
    if (!configured) {
        cudaFuncSetAttribute(gemm1_kernel,
                             cudaFuncAttributeMaxDynamicSharedMemorySize, SMEM_BYTES);
        cudaFuncSetAttribute(gemm2_kernel,
                             cudaFuncAttributeMaxDynamicSharedMemorySize, SMEM_BYTES);
        configured = 1;
    }

    cudaMemsetAsync(out, 0, (size_t)OUT_ELEMS * sizeof(float), 0);
    init_kernel<<<1, 32>>>();
    router_kernel<<<T_TOKENS, 128>>>(x, wg, out);
    build_kernel<<<1, 1>>>();
    scatter_kernel<<<T_TOKENS / 128, 128>>>();
    gemm1_kernel<<<dim3(I_DIM / BN, MAXTILES), 256, SMEM_BYTES>>>(x, w_fc, b_fc);
    gemm2_kernel<<<dim3(H_DIM / BN, MAXTILES), 256, SMEM_BYTES>>>(w_proj, b_proj, out);
    aux_kernel<<<1, 1>>>(out);
}

// round 7
// speedup vs baseline: 5.7879x; 1.5923x over previous
#include <cuda_runtime.h>
#include <cuda_fp16.h>
#include <math.h>
#include <stdint.h>

// Problem constants (fixed by setup_inputs)
#define T_TOKENS 4096
#define H_DIM    1024
#define I_DIM    4096
#define N_EXP    8
#define TOPK     2
#define OUT_ELEMS  (T_TOKENS * H_DIM)            // 4,194,304
#define LOGITS_OFF OUT_ELEMS                     // router_logits [T, E]
#define AUX_OFF    (OUT_ELEMS + T_TOKENS * N_EXP)// aux_loss scalar
#define MAXROWS  (T_TOKENS * TOPK)               // 8192 dispatched rows

#define BM 128
#define BN 128
#define BK 32                                    // K halves per stage
#define SKH 40                                   // smem row stride in halves (80B)
#define STAGES 4
#define A_STAGE_BYTES (BM * SKH * 2)             // 10240
#define B_STAGE_BYTES (BN * SKH * 2)             // 10240
#define SMEM_BYTES (STAGES * (A_STAGE_BYTES + B_STAGE_BYTES))   // 81920
#define MAXTILES 72     // worst case sum_e ceil(ne/128) <= 64 + 8

#define W_ELEMS (N_EXP * I_DIM * H_DIM)          // 33,554,432 per weight tensor

// ---------------- device scratch (no allocation allowed) ----------------
__device__ __half g_hbuf[(size_t)(MAXROWS + BM) * I_DIM];  // f16 intermediate h
__device__ __half g_xh[(size_t)T_TOKENS * H_DIM];          // f16 x
__device__ __half g_wfch[(size_t)W_ELEMS];                 // f16 w_fc
__device__ __half g_wpjh[(size_t)W_ELEMS];                 // f16 w_proj
__device__ int    g_counts[N_EXP];
__device__ int    g_offsets[N_EXP];
__device__ int    g_cursor[N_EXP];
__device__ int    g_tok[MAXROWS];
__device__ float  g_gate[MAXROWS];
__device__ int    g_top_idx[T_TOKENS * TOPK];
__device__ float  g_top_gate[T_TOKENS * TOPK];
__device__ float  g_accp[N_EXP];
__device__ float  g_zsum;
__device__ int    g_tile_e[MAXTILES];
__device__ int    g_tile_m[MAXTILES];

// ---------------- helpers ----------------
#define MMA_F16(d, a, b)                                                      \
    asm volatile("mma.sync.aligned.m16n8k16.row.col.f32.f16.f16.f32 "         \
                 "{%0,%1,%2,%3}, {%4,%5,%6,%7}, {%8,%9}, {%0,%1,%2,%3};"      \
                 : "+f"(d[0]), "+f"(d[1]), "+f"(d[2]), "+f"(d[3])             \
                 : "r"(a[0]), "r"(a[1]), "r"(a[2]), "r"(a[3]),                \
                   "r"(b[0]), "r"(b[1]))

#define CP_ASYNC16(dst, src)                                                  \
    asm volatile("cp.async.cg.shared.global [%0], [%1], 16;"                  \
                 :: "r"(dst), "l"(src))
#define CP_COMMIT() asm volatile("cp.async.commit_group;")
#define CP_WAIT2()  asm volatile("cp.async.wait_group %0;" :: "n"(STAGES - 2))
#define CP_WAIT0()  asm volatile("cp.async.wait_group 0;")

__device__ __forceinline__ unsigned smem_u32(const void* p) {
    return (unsigned)__cvta_generic_to_shared(p);
}
__device__ __forceinline__ float gelu_f(float v) {
    return 0.5f * v * (1.0f + erff(v * 0.7071067811865476f));
}

// ---------------- init ----------------
__global__ void init_kernel() {
    int i = threadIdx.x;
    if (i < N_EXP) {
        g_counts[i] = 0;
        g_cursor[i] = 0;
        g_accp[i]   = 0.f;
    }
    if (i == 0) g_zsum = 0.f;
}

// ---------------- f32 -> f16 convert (8 elems/thread/iter) ----------------
__global__ void cvt_half_kernel(const float* __restrict__ src,
                                __half* __restrict__ dst, int n8) {
    int i = blockIdx.x * blockDim.x + threadIdx.x;
    int stride = gridDim.x * blockDim.x;
    for (; i < n8; i += stride) {
        float4 v0 = ((const float4*)src)[2 * i];
        float4 v1 = ((const float4*)src)[2 * i + 1];
        __half2 h0 = __float22half2_rn(make_float2(v0.x, v0.y));
        __half2 h1 = __float22half2_rn(make_float2(v0.z, v0.w));
        __half2 h2 = __float22half2_rn(make_float2(v1.x, v1.y));
        __half2 h3 = __float22half2_rn(make_float2(v1.z, v1.w));
        uint4 o;
        o.x = *(unsigned*)&h0; o.y = *(unsigned*)&h1;
        o.z = *(unsigned*)&h2; o.w = *(unsigned*)&h3;
        ((uint4*)dst)[i] = o;
    }
}

// ---------------- router: logits, top-2 gates, aux stats ----------------
__global__ void router_kernel(const float* __restrict__ x,
                              const float* __restrict__ wg,
                              float* __restrict__ out) {
    __shared__ float sl[N_EXP];
    const int t   = blockIdx.x;
    const int tid = threadIdx.x;
    if (tid < N_EXP) sl[tid] = 0.f;
    __syncthreads();

    float p[N_EXP];
#pragma unroll
    for (int e = 0; e < N_EXP; e++) p[e] = 0.f;

    const float* xr = x + (size_t)t * H_DIM;
    for (int h = tid; h < H_DIM; h += blockDim.x) {
        float xv = xr[h];
#pragma unroll
        for (int e = 0; e < N_EXP; e++) p[e] += xv * wg[h * N_EXP + e];
    }
#pragma unroll
    for (int off = 16; off > 0; off >>= 1) {
#pragma unroll
        for (int e = 0; e < N_EXP; e++)
            p[e] += __shfl_down_sync(0xffffffffu, p[e], off);
    }
    if ((tid & 31) == 0) {
#pragma unroll
        for (int e = 0; e < N_EXP; e++) atomicAdd(&sl[e], p[e]);
    }
    __syncthreads();

    if (tid == 0) {
        float l[N_EXP];
#pragma unroll
        for (int e = 0; e < N_EXP; e++) {
            l[e] = sl[e];
            out[LOGITS_OFF + t * N_EXP + e] = l[e];
        }
        int i0 = 0; float v0 = l[0];
#pragma unroll
        for (int e = 1; e < N_EXP; e++) if (l[e] > v0) { v0 = l[e]; i0 = e; }
        int i1 = -1; float v1 = -1e30f;
#pragma unroll
        for (int e = 0; e < N_EXP; e++) if (e != i0 && l[e] > v1) { v1 = l[e]; i1 = e; }
        float g0 = 1.f / (1.f + expf(v1 - v0));
        float g1 = 1.f - g0;
        g_top_idx[2 * t]      = i0;  g_top_gate[2 * t]      = g0;
        g_top_idx[2 * t + 1]  = i1;  g_top_gate[2 * t + 1]  = g1;
        atomicAdd(&g_counts[i0], 1);
        atomicAdd(&g_counts[i1], 1);
        float m = l[0];
#pragma unroll
        for (int e = 1; e < N_EXP; e++) m = fmaxf(m, l[e]);
        float den = 0.f;
#pragma unroll
        for (int e = 0; e < N_EXP; e++) den += expf(l[e] - m);
#pragma unroll
        for (int e = 0; e < N_EXP; e++) atomicAdd(&g_accp[e], expf(l[e] - m) / den);
        float lse = m + logf(den);
        atomicAdd(&g_zsum, lse * lse);
    }
}

// ---------------- offsets + tile worklist ----------------
__global__ void build_kernel() {
    int off = 0;
    for (int e = 0; e < N_EXP; e++) { g_offsets[e] = off; off += g_counts[e]; }
    int gm = 0;
    for (int e = 0; e < N_EXP; e++) {
        int nt = (g_counts[e] + BM - 1) / BM;
        for (int i = 0; i < nt && gm < MAXTILES; i++) {
            g_tile_e[gm] = e; g_tile_m[gm] = i; gm++;
        }
    }
    for (; gm < MAXTILES; gm++) g_tile_e[gm] = -1;
}

// ---------------- scatter tokens into per-expert groups ----------------
__global__ void scatter_kernel() {
    int t = blockIdx.x * blockDim.x + threadIdx.x;
    if (t >= T_TOKENS) return;
#pragma unroll
    for (int k = 0; k < TOPK; k++) {
        int e   = g_top_idx[2 * t + k];
        int pos = atomicAdd(&g_cursor[e], 1);
        int idx = g_offsets[e] + pos;
        g_tok[idx]  = t;
        g_gate[idx] = g_top_gate[2 * t + k];
    }
}

// ==== shared GEMM body macros (f16, m16n8k16, BK=32, 4-stage cp.async) ====
// Per stage fill: A tile 128 rows x 32 halves (64B/row = 4 x 16B chunks);
// chunk c in [0,512): row=c>>2, q=c&3. Threads take chunks tid and tid+256.

#define ISSUE_STAGE(sidx, k0)                                                 \
    do {                                                                      \
        unsigned ad = aB + (unsigned)(sidx) * A_STAGE_BYTES;                  \
        unsigned bd = bB + (unsigned)(sidx) * B_STAGE_BYTES;                  \
        CP_ASYNC16(ad + aOff0, aSrc0 + (k0));                                 \
        CP_ASYNC16(ad + aOff1, aSrc1 + (k0));                                 \
        CP_ASYNC16(bd + bOff0, bSrc0 + (k0));                                 \
        CP_ASYNC16(bd + bOff1, bSrc1 + (k0));                                 \
    } while (0)

// fragment half2 word at (row, k): byte offset row*80 + k*2
#define COMPUTE_STAGE(Abase, Bbase)                                           \
    do {                                                                      \
        _Pragma("unroll")                                                     \
        for (int kk = 0; kk < BK; kk += 16) {                                 \
            unsigned a[4][4], b[4][2];                                        \
            _Pragma("unroll")                                                 \
            for (int mt = 0; mt < 4; mt++) {                                  \
                unsigned r0 = (Abase) + (wm * 64 + mt * 16 + g) * (SKH * 2)   \
                              + (kk + 2 * tg) * 2;                            \
                asm volatile("ld.shared.b32 %0, [%1];"      : "=r"(a[mt][0]) : "r"(r0));              \
                asm volatile("ld.shared.b32 %0, [%1];"      : "=r"(a[mt][1]) : "r"(r0 + 8 * SKH * 2));\
                asm volatile("ld.shared.b32 %0, [%1];"      : "=r"(a[mt][2]) : "r"(r0 + 16));         \
                asm volatile("ld.shared.b32 %0, [%1];"      : "=r"(a[mt][3]) : "r"(r0 + 8 * SKH * 2 + 16)); \
            }                                                                 \
            _Pragma("unroll")                                                 \
            for (int nt = 0; nt < 4; nt++) {                                  \
                unsigned r0 = (Bbase) + (wn * 32 + nt * 8 + g) * (SKH * 2)    \
                              + (kk + 2 * tg) * 2;                            \
                asm volatile("ld.shared.b32 %0, [%1];" : "=r"(b[nt][0]) : "r"(r0));      \
                asm volatile("ld.shared.b32 %0, [%1];" : "=r"(b[nt][1]) : "r"(r0 + 16)); \
            }                                                                 \
            _Pragma("unroll")                                                 \
            for (int mt = 0; mt < 4; mt++)                                    \
                _Pragma("unroll")                                             \
                for (int nt = 0; nt < 4; nt++)                                \
                    MMA_F16(acc[mt][nt], a[mt], b[nt]);                       \
        }                                                                     \
    } while (0)

// ---------------- GEMM1: h = gelu(x_g @ w_fc[e]^T + b) ----------------
__global__ __launch_bounds__(256) void gemm1_kernel(const float* __restrict__ b_fc) {
    const int e = g_tile_e[blockIdx.y];
    if (e < 0) return;
    const int ne   = g_counts[e];
    const int base = g_offsets[e];
    const int row0 = g_tile_m[blockIdx.y] * BM;
    const int n0   = blockIdx.x * BN;
    const __half* Bp = g_wfch + (size_t)e * I_DIM * H_DIM;

    extern __shared__ __align__(128) unsigned char dsm[];
    __shared__ int toks[BM];

    const int tid  = threadIdx.x;
    const int lane = tid & 31;
    const int wid  = tid >> 5;
    const int wm   = wid & 1;
    const int wn   = wid >> 1;
    const int g    = lane >> 2;
    const int tg   = lane & 3;

    if (tid < BM) {
        int r = row0 + tid;
        toks[tid] = g_tok[base + (r < ne ? r : 0)];
    }
    __syncthreads();

    // cp.async chunk map: chunks tid and tid+256
    const int r0c = tid >> 2,          q0 = tid & 3;
    const int r1c = (tid + 256) >> 2,  q1 = tid & 3;   // (tid+256)&3 == tid&3
    const __half* aSrc0 = g_xh + (size_t)toks[r0c] * H_DIM + q0 * 8;
    const __half* aSrc1 = g_xh + (size_t)toks[r1c] * H_DIM + q1 * 8;
    const __half* bSrc0 = Bp + (size_t)(n0 + r0c) * H_DIM + q0 * 8;
    const __half* bSrc1 = Bp + (size_t)(n0 + r1c) * H_DIM + q1 * 8;
    const unsigned aOff0 = r0c * (SKH * 2) + q0 * 16;
    const unsigned aOff1 = r1c * (SKH * 2) + q1 * 16;
    const unsigned bOff0 = aOff0, bOff1 = aOff1;

    const unsigned aB = smem_u32(dsm);
    const unsigned bB = aB + STAGES * A_STAGE_BYTES;

    float acc[4][4][4];
#pragma unroll
    for (int mt = 0; mt < 4; mt++)
#pragma unroll
        for (int nt = 0; nt < 4; nt++)
#pragma unroll
            for (int k = 0; k < 4; k++) acc[mt][nt][k] = 0.f;

    const int nIter = H_DIM / BK;    // 32
#pragma unroll
    for (int s = 0; s < STAGES - 1; s++) {
        ISSUE_STAGE(s, s * BK);
        CP_COMMIT();
    }

    for (int it = 0; it < nIter; it++) {
        CP_WAIT2();
        __syncthreads();
        int pf = it + STAGES - 1;
        if (pf < nIter) ISSUE_STAGE(pf % STAGES, pf * BK);
        CP_COMMIT();
        unsigned Abase = aB + (it % STAGES) * A_STAGE_BYTES;
        unsigned Bbase = bB + (it % STAGES) * B_STAGE_BYTES;
        COMPUTE_STAGE(Abase, Bbase);
    }
    CP_WAIT0();

    // epilogue: bias + gelu -> f16 hbuf
#pragma unroll
    for (int mt = 0; mt < 4; mt++) {
#pragma unroll
        for (int i = 0; i < 2; i++) {
            int lm = wm * 64 + mt * 16 + g + i * 8;
            int r  = row0 + lm;
            if (r < ne) {
                __half* hp = g_hbuf + (size_t)(base + r) * I_DIM;
#pragma unroll
                for (int nt = 0; nt < 4; nt++) {
                    int c = n0 + wn * 32 + nt * 8 + tg * 2;
                    float v0 = gelu_f(acc[mt][nt][i * 2 + 0] + b_fc[e * I_DIM + c]);
                    float v1 = gelu_f(acc[mt][nt][i * 2 + 1] + b_fc[e * I_DIM + c + 1]);
                    *(__half2*)(hp + c) = __float22half2_rn(make_float2(v0, v1));
                }
            }
        }
    }
}

// ---------------- GEMM2: out += gate * (h @ w_proj[e]^T + b) ----------------
__global__ __launch_bounds__(256) void gemm2_kernel(const float* __restrict__ b_proj,
                                                    float* __restrict__ out) {
    const int e = g_tile_e[blockIdx.y];
    if (e < 0) return;
    const int ne   = g_counts[e];
    const int base = g_offsets[e];
    const int row0 = g_tile_m[blockIdx.y] * BM;
    const int n0   = blockIdx.x * BN;
    const __half* Bp = g_wpjh + (size_t)e * H_DIM * I_DIM;

    extern __shared__ __align__(128) unsigned char dsm[];
    __shared__ int   toks[BM];
    __shared__ float sgate[BM];

    const int tid  = threadIdx.x;
    const int lane = tid & 31;
    const int wid  = tid >> 5;
    const int wm   = wid & 1;
    const int wn   = wid >> 1;
    const int g    = lane >> 2;
    const int tg   = lane & 3;

    if (tid < BM) {
        int r  = row0 + tid;
        int rr = (r < ne ? r : 0);
        toks[tid]  = g_tok[base + rr];
        sgate[tid] = g_gate[base + rr];
    }
    __syncthreads();

    const int r0c = tid >> 2,          q0 = tid & 3;
    const int r1c = (tid + 256) >> 2,  q1 = tid & 3;
    const __half* aSrc0 = g_hbuf + (size_t)(base + row0 + r0c) * I_DIM + q0 * 8;
    const __half* aSrc1 = g_hbuf + (size_t)(base + row0 + r1c) * I_DIM + q1 * 8;
    const __half* bSrc0 = Bp + (size_t)(n0 + r0c) * I_DIM + q0 * 8;
    const __half* bSrc1 = Bp + (size_t)(n0 + r1c) * I_DIM + q1 * 8;
    const unsigned aOff0 = r0c * (SKH * 2) + q0 * 16;
    const unsigned aOff1 = r1c * (SKH * 2) + q1 * 16;
    const unsigned bOff0 = aOff0, bOff1 = aOff1;

    const unsigned aB = smem_u32(dsm);
    const unsigned bB = aB + STAGES * A_STAGE_BYTES;

    float acc[4][4][4];
#pragma unroll
    for (int mt = 0; mt < 4; mt++)
#pragma unroll
        for (int nt = 0; nt < 4; nt++)
#pragma unroll
            for (int k = 0; k < 4; k++) acc[mt][nt][k] = 0.f;

    const int nIter = I_DIM / BK;    // 128
#pragma unroll
    for (int s = 0; s < STAGES - 1; s++) {
        ISSUE_STAGE(s, s * BK);
        CP_COMMIT();
    }

    for (int it = 0; it < nIter; it++) {
        CP_WAIT2();
        __syncthreads();
        int pf = it + STAGES - 1;
        if (pf < nIter) ISSUE_STAGE(pf % STAGES, pf * BK);
        CP_COMMIT();
        unsigned Abase = aB + (it % STAGES) * A_STAGE_BYTES;
        unsigned Bbase = bB + (it % STAGES) * B_STAGE_BYTES;
        COMPUTE_STAGE(Abase, Bbase);
    }
    CP_WAIT0();

    // epilogue: bias, gate, atomic combine into out
#pragma unroll
    for (int mt = 0; mt < 4; mt++) {
#pragma unroll
        for (int i = 0; i < 2; i++) {
            int lm = wm * 64 + mt * 16 + g + i * 8;
            int r  = row0 + lm;
            if (r < ne) {
                int   tok = toks[lm];
                float gt  = sgate[lm];
                float* orow = out + (size_t)tok * H_DIM;
#pragma unroll
                for (int nt = 0; nt < 4; nt++) {
                    int c = n0 + wn * 32 + nt * 8 + tg * 2;
                    float v0 = acc[mt][nt][i * 2 + 0] + b_proj[e * H_DIM + c];
                    float v1 = acc[mt][nt][i * 2 + 1] + b_proj[e * H_DIM + c + 1];
                    atomicAdd(orow + c,     gt * v0);
                    atomicAdd(orow + c + 1, gt * v1);
                }
            }
        }
    }
}

// ---------------- aux loss ----------------
__global__ void aux_kernel(float* __restrict__ out) {
    float sumA = 0.f, sumF = 0.f;
    for (int e = 0; e < N_EXP; e++) {
        sumA += fabsf(g_accp[e]);
        sumF += fabsf((float)g_counts[e]);
    }
    float sw = 0.f;
    for (int e = 0; e < N_EXP; e++)
        sw += (g_accp[e] / sumA) * ((float)g_counts[e] / sumF);
    sw *= (float)N_EXP;
    float z = g_zsum / (float)T_TOKENS;
    out[AUX_OFF] = sw + 0.1f * z;
}

// ---------------- launch ----------------
extern "C" void kernel_launch(void* const* d_in, const int* in_sizes, int n_in,
                              void* d_out, int out_size) {
    const float* x      = (const float*)d_in[0];
    const float* wg     = (const float*)d_in[1];
    const float* w_fc   = (const float*)d_in[2];
    const float* b_fc   = (const float*)d_in[3];
    const float* w_proj = (const float*)d_in[4];
    const float* b_proj = (const float*)d_in[5];
    float* out = (float*)d_out;

    static int configured = 0;
    if (!configured) {
        cudaFuncSetAttribute(gemm1_kernel,
                             cudaFuncAttributeMaxDynamicSharedMemorySize, SMEM_BYTES);
        cudaFuncSetAttribute(gemm2_kernel,
                             cudaFuncAttributeMaxDynamicSharedMemorySize, SMEM_BYTES);
        configured = 1;
    }

    __half* xh; __half* wfch; __half* wpjh;
    cudaGetSymbolAddress((void**)&xh,   g_xh);
    cudaGetSymbolAddress((void**)&wfch, g_wfch);
    cudaGetSymbolAddress((void**)&wpjh, g_wpjh);

    cudaMemsetAsync(out, 0, (size_t)OUT_ELEMS * sizeof(float), 0);
    init_kernel<<<1, 32>>>();
    cvt_half_kernel<<<2048, 256>>>(x,      xh,   (T_TOKENS * H_DIM) / 8);
    cvt_half_kernel<<<4096, 256>>>(w_fc,   wfch, W_ELEMS / 8);
    cvt_half_kernel<<<4096, 256>>>(w_proj, wpjh, W_ELEMS / 8);
    router_kernel<<<T_TOKENS, 128>>>(x, wg, out);
    build_kernel<<<1, 1>>>();
    scatter_kernel<<<T_TOKENS / 128, 128>>>();
    gemm1_kernel<<<dim3(I_DIM / BN, MAXTILES), 256, SMEM_BYTES>>>(b_fc);
    gemm2_kernel<<<dim3(H_DIM / BN, MAXTILES), 256, SMEM_BYTES>>>(b_proj, out);
    aux_kernel<<<1, 1>>>(out);
}